// round 4
// baseline (speedup 1.0000x reference)
#include <cuda_runtime.h>

#define BB 8
#define NN 256
#define HH 128
#define EPSF 1e-20f

// Scratch (allocation-free rule: __device__ globals)
__device__ float g_Ux[BB * NN * HH];
__device__ float g_Vx[BB * NN * HH];

// ---------------------------------------------------------------------------
// Kernel 1: Ux = mask*(x@Uw^T + Ub), Vx = mask*(x@Vw^T + Vb)
// grid 256 x 256 threads. Block owns R=8 rows. Thread t: o = t&127 (feature),
// sel = t>>7 (0 -> U, 1 -> V). Halved per-thread dependent work vs R3 and
// halved redundant weight L2 traffic (256 blocks x 128 KB = 32 MB).
// ---------------------------------------------------------------------------
__global__ __launch_bounds__(256) void linear_kernel(
    const float* __restrict__ x, const float* __restrict__ mask,
    const float* __restrict__ Uw, const float* __restrict__ Ub,
    const float* __restrict__ Vw, const float* __restrict__ Vb)
{
    const int R = 8;
    __shared__ float4 xs[R][HH / 4];
    const int row0 = blockIdx.x * R;
    const int t   = threadIdx.x;
    const int o   = t & 127;
    const int sel = t >> 7;

    // R*HH = 1024 floats = 256 float4 -> one per thread
    reinterpret_cast<float4*>(xs)[t] =
        reinterpret_cast<const float4*>(x + (size_t)row0 * HH)[t];
    __syncthreads();

    const float* W  = sel ? Vw : Uw;
    const float  bb = sel ? Vb[o] : Ub[o];
    const float4* W4 = reinterpret_cast<const float4*>(W + (size_t)o * HH);
    float* dst = sel ? g_Vx : g_Ux;

    float acc[R];
#pragma unroll
    for (int r = 0; r < R; r++) acc[r] = 0.f;

#pragma unroll 8
    for (int k4 = 0; k4 < HH / 4; k4++) {
        const float4 w = W4[k4];
#pragma unroll
        for (int r = 0; r < R; r++) {
            const float4 xr = xs[r][k4];  // broadcast LDS.128
            acc[r] = fmaf(xr.x, w.x, fmaf(xr.y, w.y, fmaf(xr.z, w.z, fmaf(xr.w, w.w, acc[r]))));
        }
    }

#pragma unroll
    for (int r = 0; r < R; r++) {
        const int row = row0 + r;
        dst[(size_t)row * HH + o] = mask[row] * (acc[r] + bb);
    }
}

// ---------------------------------------------------------------------------
// Kernel 2: out[b,i,h] = Ux + (mi*sum_j eg*mj*Vx[j]) / (EPS + mi*sum_j eg*mj)
// WARP-PER-TILE: grid 512 x 128 threads (4 warps). Warp w owns tile
// bi = blockIdx.x*4 + w entirely: lane = h4 float4 slice, private j-loop over
// all 256 sources. Reduction is thread-local -> NO smem reduction, NO
// syncthreads in the hot path, no idle-warp epilogue (R3's 8 block drains
// per block are gone). Each warp streams a sequential 128KB eg region;
// unroll 8 -> 4KB in flight per warp. __ldcs streams read-once eg past L2;
// Vx (128KB per b) stays L1/L2-hot across the block's 4 warps.
// ---------------------------------------------------------------------------
__global__ __launch_bounds__(128) void edge_kernel(
    const float* __restrict__ eg, const float* __restrict__ mask,
    float* __restrict__ out)
{
    const int t  = threadIdx.x;
    const int h4 = t & 31;
    const int w  = t >> 5;               // warp id 0..3
    const int bi = blockIdx.x * 4 + w;   // tile owned by this warp
    const int b  = bi >> 8;              // 4 | 256 -> same b across block
    const int i  = bi & 255;

    __shared__ float msk[NN];
    if (t < NN) { /* 128 threads */ }
    msk[t] = mask[b * NN + t];
    msk[t + 128] = mask[b * NN + t + 128];
    __syncthreads();                     // one sync total

    const float4* egp = reinterpret_cast<const float4*>(eg) + (size_t)bi * NN * (HH / 4) + h4;
    const float4* vxp = reinterpret_cast<const float4*>(g_Vx) + (size_t)b * NN * (HH / 4) + h4;

    float4 s0 = make_float4(0.f, 0.f, 0.f, 0.f);
    float4 s1 = make_float4(0.f, 0.f, 0.f, 0.f);

#pragma unroll 8
    for (int j = 0; j < NN; j++) {
        float4 e = __ldcs(egp + (size_t)j * (HH / 4));
        const float4 v = __ldg(vxp + (size_t)j * (HH / 4));
        const float mj = msk[j];
        e.x *= mj; e.y *= mj; e.z *= mj; e.w *= mj;
        s0.x += e.x; s0.y += e.y; s0.z += e.z; s0.w += e.w;
        s1.x = fmaf(e.x, v.x, s1.x);
        s1.y = fmaf(e.y, v.y, s1.y);
        s1.z = fmaf(e.z, v.z, s1.z);
        s1.w = fmaf(e.w, v.w, s1.w);
    }

    const float mi = msk[i];
    const float4 ux = reinterpret_cast<const float4*>(g_Ux)[(size_t)bi * (HH / 4) + h4];
    float4 o;
    o.x = ux.x + (mi * s1.x) / (EPSF + mi * s0.x);
    o.y = ux.y + (mi * s1.y) / (EPSF + mi * s0.y);
    o.z = ux.z + (mi * s1.z) / (EPSF + mi * s0.z);
    o.w = ux.w + (mi * s1.w) / (EPSF + mi * s0.w);
    reinterpret_cast<float4*>(out)[(size_t)bi * (HH / 4) + h4] = o;
}

extern "C" void kernel_launch(void* const* d_in, const int* in_sizes, int n_in,
                              void* d_out, int out_size)
{
    const float* x   = (const float*)d_in[0];
    const float* eg  = (const float*)d_in[1];
    const float* msk = (const float*)d_in[2];
    const float* Uw  = (const float*)d_in[3];
    const float* Ub  = (const float*)d_in[4];
    const float* Vw  = (const float*)d_in[5];
    const float* Vb  = (const float*)d_in[6];
    float* out = (float*)d_out;

    linear_kernel<<<(BB * NN) / 8, 256>>>(x, msk, Uw, Ub, Vw, Vb);
    edge_kernel<<<(BB * NN) / 4, 128>>>(eg, msk, out);
}

// round 5
// speedup vs baseline: 1.1943x; 1.1943x over previous
#include <cuda_runtime.h>

#define BB 8
#define NN 256
#define HH 128
#define EPSF 1e-20f

// Scratch (allocation-free rule: __device__ globals)
__device__ float g_Ux[BB * NN * HH];
__device__ float g_Vx[BB * NN * HH];

// ---------------------------------------------------------------------------
// Kernel 1: Ux = mask*(x@Uw^T + Ub), Vx = mask*(x@Vw^T + Vb)
// grid 256 x 256 threads. Block owns R=8 rows; thread t: o = t&127 (feature),
// sel = t>>7 (0 -> U, 1 -> V).
// ---------------------------------------------------------------------------
__global__ __launch_bounds__(256) void linear_kernel(
    const float* __restrict__ x, const float* __restrict__ mask,
    const float* __restrict__ Uw, const float* __restrict__ Ub,
    const float* __restrict__ Vw, const float* __restrict__ Vb)
{
    const int R = 8;
    __shared__ float4 xs[R][HH / 4];
    const int row0 = blockIdx.x * R;
    const int t   = threadIdx.x;
    const int o   = t & 127;
    const int sel = t >> 7;

    reinterpret_cast<float4*>(xs)[t] =
        reinterpret_cast<const float4*>(x + (size_t)row0 * HH)[t];
    __syncthreads();

    const float* W  = sel ? Vw : Uw;
    const float  bb = sel ? Vb[o] : Ub[o];
    const float4* W4 = reinterpret_cast<const float4*>(W + (size_t)o * HH);
    float* dst = sel ? g_Vx : g_Ux;

    float acc[R];
#pragma unroll
    for (int r = 0; r < R; r++) acc[r] = 0.f;

#pragma unroll 8
    for (int k4 = 0; k4 < HH / 4; k4++) {
        const float4 w = W4[k4];
#pragma unroll
        for (int r = 0; r < R; r++) {
            const float4 xr = xs[r][k4];
            acc[r] = fmaf(xr.x, w.x, fmaf(xr.y, w.y, fmaf(xr.z, w.z, fmaf(xr.w, w.w, acc[r]))));
        }
    }

#pragma unroll
    for (int r = 0; r < R; r++) {
        const int row = row0 + r;
        dst[(size_t)row * HH + o] = mask[row] * (acc[r] + bb);
    }
}

// ---------------------------------------------------------------------------
// Kernel 2: out[b,i,h] = Ux + (mi*sum_j eg*mj*Vx[j]) / (EPS + mi*sum_j eg*mj)
// J-SPLIT WARP-PER-TILE: block = 256 thr = 8 warps = 2 tiles x 4 j-quarters.
// grid = 1024 -> 7 blocks/SM resident = 87% occ, single wave (7*148 >= 1024).
// Each warp streams 64 consecutive j rows (32KB sequential eg) with lane =
// float4 h-slice; partials combined once via smem (ONE syncthreads total,
// unlike R3's 8 serial drains). R4 lesson: DRAM% tracks warp count -> 8192
// warps here vs R4's 2048.
// ---------------------------------------------------------------------------
__global__ __launch_bounds__(256) void edge_kernel(
    const float* __restrict__ eg, const float* __restrict__ mask,
    float* __restrict__ out)
{
    const int t    = threadIdx.x;
    const int lane = t & 31;
    const int w    = t >> 5;            // 0..7
    const int tw   = w >> 2;            // tile within block: 0..1
    const int q    = w & 3;             // j-quarter: 0..3
    const int bi   = blockIdx.x * 2 + tw;
    const int b    = bi >> 8;           // 2 | 256 -> same b for both tiles

    __shared__ float  msk[NN];
    __shared__ float4 sh0[8][32];
    __shared__ float4 sh1[8][32];

    msk[t] = mask[b * NN + t];          // 256 threads, NN = 256
    __syncthreads();

    const float4* egp = reinterpret_cast<const float4*>(eg) + (size_t)bi * NN * (HH / 4) + lane;
    const float4* vxp = reinterpret_cast<const float4*>(g_Vx) + (size_t)b * NN * (HH / 4) + lane;

    float4 s0 = make_float4(0.f, 0.f, 0.f, 0.f);
    float4 s1 = make_float4(0.f, 0.f, 0.f, 0.f);

    const int j0 = q * 64;
#pragma unroll 8
    for (int jj = 0; jj < 64; jj++) {
        const int j = j0 + jj;
        float4 e = __ldcs(egp + (size_t)j * (HH / 4));
        const float4 v = __ldg(vxp + (size_t)j * (HH / 4));
        const float mj = msk[j];
        e.x *= mj; e.y *= mj; e.z *= mj; e.w *= mj;
        s0.x += e.x; s0.y += e.y; s0.z += e.z; s0.w += e.w;
        s1.x = fmaf(e.x, v.x, s1.x);
        s1.y = fmaf(e.y, v.y, s1.y);
        s1.z = fmaf(e.z, v.z, s1.z);
        s1.w = fmaf(e.w, v.w, s1.w);
    }

    sh0[w][lane] = s0;
    sh1[w][lane] = s1;
    __syncthreads();

    if (t < 64) {
        const int tile = t >> 5;        // 0..1
        const int l    = t & 31;
        const int base = tile * 4;
        float4 a0 = sh0[base][l];
        float4 a1 = sh1[base][l];
#pragma unroll
        for (int k = 1; k < 4; k++) {
            const float4 b0 = sh0[base + k][l];
            const float4 b1 = sh1[base + k][l];
            a0.x += b0.x; a0.y += b0.y; a0.z += b0.z; a0.w += b0.w;
            a1.x += b1.x; a1.y += b1.y; a1.z += b1.z; a1.w += b1.w;
        }
        const int bi2 = blockIdx.x * 2 + tile;
        const float mi = msk[bi2 & 255];
        const float4 ux = reinterpret_cast<const float4*>(g_Ux)[(size_t)bi2 * (HH / 4) + l];
        float4 o;
        o.x = ux.x + (mi * a1.x) / (EPSF + mi * a0.x);
        o.y = ux.y + (mi * a1.y) / (EPSF + mi * a0.y);
        o.z = ux.z + (mi * a1.z) / (EPSF + mi * a0.z);
        o.w = ux.w + (mi * a1.w) / (EPSF + mi * a0.w);
        reinterpret_cast<float4*>(out)[(size_t)bi2 * (HH / 4) + l] = o;
    }
}

extern "C" void kernel_launch(void* const* d_in, const int* in_sizes, int n_in,
                              void* d_out, int out_size)
{
    const float* x   = (const float*)d_in[0];
    const float* eg  = (const float*)d_in[1];
    const float* msk = (const float*)d_in[2];
    const float* Uw  = (const float*)d_in[3];
    const float* Ub  = (const float*)d_in[4];
    const float* Vw  = (const float*)d_in[5];
    const float* Vb  = (const float*)d_in[6];
    float* out = (float*)d_out;

    linear_kernel<<<(BB * NN) / 8, 256>>>(x, msk, Uw, Ub, Vw, Vb);
    edge_kernel<<<(BB * NN) / 2, 256>>>(eg, msk, out);
}

// round 6
// speedup vs baseline: 1.2336x; 1.0328x over previous
#include <cuda_runtime.h>

#define BB 8
#define NN 256
#define HH 128
#define EPSF 1e-20f

// Scratch (allocation-free rule: __device__ globals)
__device__ float g_Ux[BB * NN * HH];
__device__ float g_Vx[BB * NN * HH];

__device__ __forceinline__ float dot4(float4 a, float4 b, float c) {
    return fmaf(a.x, b.x, fmaf(a.y, b.y, fmaf(a.z, b.z, fmaf(a.w, b.w, c))));
}

// ---------------------------------------------------------------------------
// Kernel 1 (rewritten): 2D-tiled linear. grid = (64 row-tiles x 8 o-tiles),
// 256 thr. Block: 32 rows x 32 outputs of one matrix (y<4 -> U, else V).
// x slab staged in smem (row stride 33 float4; threads own rows rg, rg+8,
// rg+16, rg+24 -> 8 distinct bank groups, conflict-free). Fixes R5's two
// linear sinks: 1.73 blocks/SM imbalance and 32MB redundant weight traffic
// (now ~16MB total L2, 512 balanced blocks).
// ---------------------------------------------------------------------------
__global__ __launch_bounds__(256) void linear_kernel(
    const float* __restrict__ x, const float* __restrict__ mask,
    const float* __restrict__ Uw, const float* __restrict__ Ub,
    const float* __restrict__ Vw, const float* __restrict__ Vb)
{
    __shared__ float4 xs[32 * 33];
    const int t  = threadIdx.x;
    const int r0 = blockIdx.x * 32;
    const int yt = blockIdx.y;                 // 0..7
    const int o  = ((yt & 3) << 5) + (t >> 3); // output feature 0..127
    const int rg = t & 7;

    // stage 32 rows x 128 floats = 1024 float4
#pragma unroll
    for (int s = 0; s < 4; s++) {
        const int idx = t + s * 256;
        const int row = idx >> 5, c4 = idx & 31;
        xs[row * 33 + c4] = reinterpret_cast<const float4*>(x)[(size_t)(r0 + row) * 32 + c4];
    }
    __syncthreads();

    const bool isU = (yt < 4);
    const float4* W4 = reinterpret_cast<const float4*>(isU ? Uw : Vw) + (size_t)o * 32;
    const float bias = isU ? Ub[o] : Vb[o];
    float* dst = isU ? g_Ux : g_Vx;

    float a0 = 0.f, a1 = 0.f, a2 = 0.f, a3 = 0.f;
#pragma unroll 8
    for (int k4 = 0; k4 < 32; k4++) {
        const float4 wv = W4[k4];
        a0 = dot4(xs[(rg     ) * 33 + k4], wv, a0);
        a1 = dot4(xs[(rg +  8) * 33 + k4], wv, a1);
        a2 = dot4(xs[(rg + 16) * 33 + k4], wv, a2);
        a3 = dot4(xs[(rg + 24) * 33 + k4], wv, a3);
    }

    float acc[4] = {a0, a1, a2, a3};
#pragma unroll
    for (int r = 0; r < 4; r++) {
        const int row = r0 + rg + r * 8;
        dst[(size_t)row * HH + o] = mask[row] * (acc[r] + bias);
    }
}

// ---------------------------------------------------------------------------
// Kernel 2: out[b,i,h] = Ux + (mi*sum_j eg*mj*Vx[j]) / (EPS + mi*sum_j eg*mj)
// R5 layout (2 tiles x 4 j-quarters per 256-thr block, grid 1024) but with
// __launch_bounds__(256, 7): 36-reg budget -> 7 blocks/SM -> capacity 1036 >=
// 1024 -> SINGLE WAVE at ~86% occ (R5: regs=44 -> 5/SM -> 740+284 two-wave,
// occ 49%). Pointer-increment addressing cuts IMAD + live regs.
// ---------------------------------------------------------------------------
__global__ __launch_bounds__(256, 7) void edge_kernel(
    const float* __restrict__ eg, const float* __restrict__ mask,
    float* __restrict__ out)
{
    const int t    = threadIdx.x;
    const int lane = t & 31;
    const int w    = t >> 5;            // 0..7
    const int tw   = w >> 2;            // tile in block: 0..1
    const int q    = w & 3;             // j-quarter: 0..3
    const int bi   = blockIdx.x * 2 + tw;
    const int b    = bi >> 8;           // same b for both tiles (2 | 256)

    __shared__ float  msk[NN];
    __shared__ float4 sh0[8][32];
    __shared__ float4 sh1[8][32];

    msk[t] = mask[b * NN + t];
    __syncthreads();

    const float4* egp = reinterpret_cast<const float4*>(eg)
                        + (size_t)(bi * NN + q * 64) * (HH / 4) + lane;
    const float4* vxp = reinterpret_cast<const float4*>(g_Vx)
                        + (size_t)(b * NN + q * 64) * (HH / 4) + lane;
    const float* mp = &msk[q * 64];

    float4 s0 = make_float4(0.f, 0.f, 0.f, 0.f);
    float4 s1 = make_float4(0.f, 0.f, 0.f, 0.f);

#pragma unroll 4
    for (int jj = 0; jj < 64; jj++) {
        float4 e = __ldcs(egp); egp += HH / 4;
        const float4 v = *vxp;  vxp += HH / 4;
        const float mj = mp[jj];
        e.x *= mj; e.y *= mj; e.z *= mj; e.w *= mj;
        s0.x += e.x; s0.y += e.y; s0.z += e.z; s0.w += e.w;
        s1.x = fmaf(e.x, v.x, s1.x);
        s1.y = fmaf(e.y, v.y, s1.y);
        s1.z = fmaf(e.z, v.z, s1.z);
        s1.w = fmaf(e.w, v.w, s1.w);
    }

    sh0[w][lane] = s0;
    sh1[w][lane] = s1;
    __syncthreads();

    if (t < 64) {
        const int tile = t >> 5;        // 0..1
        const int l    = t & 31;
        const int base = tile * 4;
        float4 a0 = sh0[base][l];
        float4 a1 = sh1[base][l];
#pragma unroll
        for (int k = 1; k < 4; k++) {
            const float4 b0 = sh0[base + k][l];
            const float4 b1 = sh1[base + k][l];
            a0.x += b0.x; a0.y += b0.y; a0.z += b0.z; a0.w += b0.w;
            a1.x += b1.x; a1.y += b1.y; a1.z += b1.z; a1.w += b1.w;
        }
        const int bi2 = blockIdx.x * 2 + tile;
        const float mi = msk[bi2 & 255];
        const float4 ux = reinterpret_cast<const float4*>(g_Ux)[(size_t)bi2 * (HH / 4) + l];
        float4 o;
        o.x = ux.x + (mi * a1.x) / (EPSF + mi * a0.x);
        o.y = ux.y + (mi * a1.y) / (EPSF + mi * a0.y);
        o.z = ux.z + (mi * a1.z) / (EPSF + mi * a0.z);
        o.w = ux.w + (mi * a1.w) / (EPSF + mi * a0.w);
        reinterpret_cast<float4*>(out)[(size_t)bi2 * (HH / 4) + l] = o;
    }
}

extern "C" void kernel_launch(void* const* d_in, const int* in_sizes, int n_in,
                              void* d_out, int out_size)
{
    const float* x   = (const float*)d_in[0];
    const float* eg  = (const float*)d_in[1];
    const float* msk = (const float*)d_in[2];
    const float* Uw  = (const float*)d_in[3];
    const float* Ub  = (const float*)d_in[4];
    const float* Vw  = (const float*)d_in[5];
    const float* Vb  = (const float*)d_in[6];
    float* out = (float*)d_out;

    dim3 lgrid(64, 8);
    linear_kernel<<<lgrid, 256>>>(x, msk, Uw, Ub, Vw, Vb);
    edge_kernel<<<(BB * NN) / 2, 256>>>(eg, msk, out);
}